// round 4
// baseline (speedup 1.0000x reference)
#include <cuda_runtime.h>

// Kwta: per-sample exact k-th-largest threshold + mask + NCHW-flat "reshape" permutation.
// x: [32, 56, 56, 256] f32.  dim = 802816, k = ceil(0.2*dim) = 160564.
// out[b*dim + c*3136 + hw] = thresholded x[b*dim + hw*256 + c]  (3136x256 transpose per sample).

#define BATCH 32
#define HW    3136
#define CH    256
#define DIM   802816
#define KSEL  160564u
#define NB    2048
#define CAP   131072u   // candidate capacity per sample (~4.5x expected 28.7k)

__device__ unsigned int g_hist[2][BATCH][NB];
__device__ unsigned int g_ccount[BATCH];
__device__ unsigned int g_prefix[BATCH];
__device__ unsigned int g_krem[BATCH];
__device__ float        g_thresh[BATCH];
__device__ float        g_cand[BATCH][CAP];

// Order-preserving bijection f32 bits -> u32 (ascending).
__device__ __forceinline__ unsigned int fkey(float f) {
    unsigned int u = __float_as_uint(f);
    return (u & 0x80000000u) ? ~u : (u ^ 0x80000000u);
}

__global__ void zero_kernel() {
    int i = blockIdx.x * blockDim.x + threadIdx.x;
    int nh = 2 * BATCH * NB;
    if (i < nh) (&g_hist[0][0][0])[i] = 0u;
    if (i < BATCH) g_ccount[i] = 0u;
}

// Pass 0: 11-bit (sign+exp+2mant) histogram. Cheap bin math, no full fkey.
__global__ void hist0_kernel(const float* __restrict__ x) {
    __shared__ unsigned int sh[NB];
    const int b = blockIdx.y;
    for (int j = threadIdx.x; j < NB; j += blockDim.x) sh[j] = 0u;
    __syncthreads();

    const uint4* __restrict__ p4 = reinterpret_cast<const uint4*>(x + (size_t)b * DIM);
    const int n4 = DIM / 4;
    const int stride = gridDim.x * blockDim.x;
    for (int i = blockIdx.x * blockDim.x + threadIdx.x; i < n4; i += stride) {
        uint4 v = p4[i];
        unsigned int u[4] = {v.x, v.y, v.z, v.w};
#pragma unroll
        for (int j = 0; j < 4; j++) {
            unsigned int t = u[j] >> 21;                    // sign|exp|2 mantissa bits
            unsigned int bin = (t < 1024u) ? (t + 1024u) : (2047u - t);
            atomicAdd(&sh[bin], 1u);
        }
    }
    __syncthreads();
    for (int j = threadIdx.x; j < NB; j += blockDim.x) {
        unsigned int c = sh[j];
        if (c) atomicAdd(&g_hist[0][b][j], c);
    }
}

// Parallel bin scan: block per sample, 256 threads x 8 bins, descending order.
// Finds the bin containing the k-th largest; updates prefix/krem.
__global__ void scan_kernel(int pass) {
    const int b = blockIdx.x;
    const int t = threadIdx.x;                 // 256 threads
    const unsigned int* __restrict__ h = g_hist[pass][b];

    const int base = NB - 8 * (t + 1);         // thread t owns bins [base, base+8), t=0 = top
    unsigned int c[8], lsum = 0;
#pragma unroll
    for (int j = 0; j < 8; j++) { c[j] = h[base + j]; lsum += c[j]; }

    __shared__ unsigned int ssum[256];
    ssum[t] = lsum;
    __syncthreads();
    unsigned int v = lsum;
    for (int off = 1; off < 256; off <<= 1) {
        unsigned int u = (t >= off) ? ssum[t - off] : 0u;
        __syncthreads();
        v += u;
        ssum[t] = v;
        __syncthreads();
    }
    unsigned int ex = v - lsum;                // total count in bins above this segment

    const unsigned int k = (pass == 0) ? KSEL : g_krem[b];
    if (ex < k && ex + lsum >= k) {            // exactly one thread
        unsigned int cum = ex; int sel = 0; unsigned int kk = 0;
#pragma unroll
        for (int j = 7; j >= 0; j--) {
            cum += c[j];
            if (cum >= k) { sel = base + j; kk = k - (cum - c[j]); break; }
        }
        if (pass == 0) {
            g_prefix[b] = ((unsigned int)sel) << 21;
        } else {
            g_prefix[b] |= ((unsigned int)sel) << 10;
        }
        g_krem[b] = kk;
    }
}

// Pass 1: filter by 11-bit prefix; build 11-bit mid histogram AND compact
// matching values into g_cand (warp-aggregated counter increments).
__global__ void compact_hist1_kernel(const float* __restrict__ x) {
    __shared__ unsigned int sh[NB];
    const int b = blockIdx.y;
    for (int j = threadIdx.x; j < NB; j += blockDim.x) sh[j] = 0u;
    __syncthreads();

    const unsigned int ptop = g_prefix[b] >> 21;
    const float4* __restrict__ p4 = reinterpret_cast<const float4*>(x + (size_t)b * DIM);
    const int n4 = DIM / 4;
    const int stride = gridDim.x * blockDim.x;
    const int lane = threadIdx.x & 31;

    for (int i = blockIdx.x * blockDim.x + threadIdx.x; i < n4; i += stride) {
        float4 v = p4[i];
        float vals[4] = {v.x, v.y, v.z, v.w};
#pragma unroll
        for (int j = 0; j < 4; j++) {
            unsigned int key = fkey(vals[j]);
            bool hit = ((key >> 21) == ptop);
            unsigned int am = __activemask();
            unsigned int bal = __ballot_sync(am, hit);
            if (hit) {
                atomicAdd(&sh[(key >> 10) & 0x7FFu], 1u);
                int leader = __ffs(bal) - 1;
                unsigned int pos;
                if (lane == leader) pos = atomicAdd(&g_ccount[b], __popc(bal));
                pos = __shfl_sync(bal, pos, leader);
                pos += __popc(bal & ((1u << lane) - 1u));
                if (pos < CAP) g_cand[b][pos] = vals[j];
            }
        }
    }
    __syncthreads();
    for (int j = threadIdx.x; j < NB; j += blockDim.x) {
        unsigned int c = sh[j];
        if (c) atomicAdd(&g_hist[1][b][j], c);
    }
}

// Pass 2 fused with its scan: block per sample over compacted candidates only.
// 1024-bin low-10-bit histogram in shared, then descending scan -> threshold.
__global__ void final_kernel() {
    __shared__ unsigned int sh[1024];
    __shared__ unsigned int ssum[256];
    const int b = blockIdx.x;
    const int t = threadIdx.x;                 // 256 threads
#pragma unroll
    for (int j = 0; j < 4; j++) sh[t + 256 * j] = 0u;
    __syncthreads();

    const unsigned int pref = g_prefix[b];
    const unsigned int n = min(g_ccount[b], CAP);
    for (unsigned int i = t; i < n; i += 256) {
        unsigned int key = fkey(g_cand[b][i]);
        if ((key >> 10) == (pref >> 10)) atomicAdd(&sh[key & 0x3FFu], 1u);
    }
    __syncthreads();

    const int base = 1024 - 4 * (t + 1);       // thread t owns 4 bins, t=0 = top
    unsigned int c[4], lsum = 0;
#pragma unroll
    for (int j = 0; j < 4; j++) { c[j] = sh[base + j]; lsum += c[j]; }

    ssum[t] = lsum;
    __syncthreads();
    unsigned int v = lsum;
    for (int off = 1; off < 256; off <<= 1) {
        unsigned int u = (t >= off) ? ssum[t - off] : 0u;
        __syncthreads();
        v += u;
        ssum[t] = v;
        __syncthreads();
    }
    unsigned int ex = v - lsum;

    const unsigned int k = g_krem[b];
    if (ex < k && ex + lsum >= k) {
        unsigned int cum = ex; int sel = 0;
#pragma unroll
        for (int j = 3; j >= 0; j--) {
            cum += c[j];
            if (cum >= k) { sel = base + j; break; }
        }
        unsigned int full = pref | (unsigned int)sel;
        unsigned int u = (full & 0x80000000u) ? (full ^ 0x80000000u) : ~full;
        g_thresh[b] = __uint_as_float(u);
    }
}

// Fused threshold + 3136x256 -> 256x3136 transpose, 32x32 shared tiles.
__global__ void mask_transpose_kernel(const float* __restrict__ x,
                                      float* __restrict__ out) {
    __shared__ float tile[32][33];
    const int b   = blockIdx.z;
    const float t = g_thresh[b];
    const int c0  = blockIdx.x * 32;
    const int hw0 = blockIdx.y * 32;
    const float* __restrict__ in = x + (size_t)b * DIM;
    float* __restrict__ o        = out + (size_t)b * DIM;

#pragma unroll
    for (int j = 0; j < 32; j += 8) {
        tile[threadIdx.y + j][threadIdx.x] =
            in[(size_t)(hw0 + threadIdx.y + j) * CH + c0 + threadIdx.x];
    }
    __syncthreads();
#pragma unroll
    for (int j = 0; j < 32; j += 8) {
        float v = tile[threadIdx.x][threadIdx.y + j];
        o[(size_t)(c0 + threadIdx.y + j) * HW + hw0 + threadIdx.x] =
            (v < t) ? 0.0f : v;
    }
}

extern "C" void kernel_launch(void* const* d_in, const int* in_sizes, int n_in,
                              void* d_out, int out_size) {
    const float* x = (const float*)d_in[0];
    float* out = (float*)d_out;

    zero_kernel<<<(2 * BATCH * NB + 255) / 256, 256>>>();

    hist0_kernel<<<dim3(32, BATCH), 256>>>(x);
    scan_kernel<<<BATCH, 256>>>(0);
    compact_hist1_kernel<<<dim3(32, BATCH), 256>>>(x);
    scan_kernel<<<BATCH, 256>>>(1);
    final_kernel<<<BATCH, 256>>>();

    mask_transpose_kernel<<<dim3(CH / 32, HW / 32, BATCH), dim3(32, 8)>>>(x, out);
}

// round 6
// speedup vs baseline: 4.1418x; 4.1418x over previous
#include <cuda_runtime.h>

// Kwta: per-sample exact k-th-largest threshold + mask + NCHW-flat "reshape" permutation.
// x: [32, 56, 56, 256] f32.  dim = 802816, k = ceil(0.2*dim) = 160564.
// out[b*dim + c*3136 + hw] = thresholded x[b*dim + hw*256 + c]  (3136x256 transpose per sample).

#define BATCH 32
#define HW    3136
#define CH    256
#define DIM   802816
#define KSEL  160564u
#define NB    2048

__device__ unsigned int g_hist[3][BATCH][NB];
__device__ unsigned int g_prefix[BATCH];
__device__ unsigned int g_krem[BATCH];
__device__ float        g_thresh[BATCH];

// Order-preserving bijection f32 bits -> u32 (ascending).
__device__ __forceinline__ unsigned int fkey(float f) {
    unsigned int u = __float_as_uint(f);
    return (u & 0x80000000u) ? ~u : (u ^ 0x80000000u);
}

__global__ void zero_kernel() {
    int i = blockIdx.x * blockDim.x + threadIdx.x;
    int nh = 3 * BATCH * NB;
    if (i < nh) (&g_hist[0][0][0])[i] = 0u;
}

// Pass 0: top-11-bit histogram with cheap bin math (equivalent to fkey>>21).
__global__ void hist0_kernel(const float* __restrict__ x) {
    __shared__ unsigned int sh[NB];
    const int b = blockIdx.y;
    for (int j = threadIdx.x; j < NB; j += blockDim.x) sh[j] = 0u;
    __syncthreads();

    const uint4* __restrict__ p4 = reinterpret_cast<const uint4*>(x + (size_t)b * DIM);
    const int n4 = DIM / 4;
    const int stride = gridDim.x * blockDim.x;
    for (int i = blockIdx.x * blockDim.x + threadIdx.x; i < n4; i += stride) {
        uint4 v = p4[i];
        unsigned int u[4] = {v.x, v.y, v.z, v.w};
#pragma unroll
        for (int j = 0; j < 4; j++) {
            unsigned int t = u[j] >> 21;
            unsigned int bin = (t < 1024u) ? (t + 1024u) : (2047u - t);
            atomicAdd(&sh[bin], 1u);
        }
    }
    __syncthreads();
    for (int j = threadIdx.x; j < NB; j += blockDim.x) {
        unsigned int c = sh[j];
        if (c) atomicAdd(&g_hist[0][b][j], c);
    }
}

// Passes 1 and 2: filter by narrowed prefix, histogram next digit.
template <int PASS>
__global__ void hist_kernel(const float* __restrict__ x) {
    __shared__ unsigned int sh[NB];
    const int b = blockIdx.y;
    for (int j = threadIdx.x; j < NB; j += blockDim.x) sh[j] = 0u;
    __syncthreads();

    const unsigned int pref = g_prefix[b];
    const float4* __restrict__ p4 = reinterpret_cast<const float4*>(x + (size_t)b * DIM);
    const int n4 = DIM / 4;
    const int stride = gridDim.x * blockDim.x;

    for (int i = blockIdx.x * blockDim.x + threadIdx.x; i < n4; i += stride) {
        float4 v = p4[i];
        float vals[4] = {v.x, v.y, v.z, v.w};
#pragma unroll
        for (int j = 0; j < 4; j++) {
            unsigned int key = fkey(vals[j]);
            if (PASS == 1) {
                if ((key >> 21) == (pref >> 21))
                    atomicAdd(&sh[(key >> 10) & 0x7FFu], 1u);
            } else {
                if ((key >> 10) == (pref >> 10))
                    atomicAdd(&sh[key & 0x3FFu], 1u);
            }
        }
    }
    __syncthreads();
    for (int j = threadIdx.x; j < NB; j += blockDim.x) {
        unsigned int c = sh[j];
        if (c) atomicAdd(&g_hist[PASS][b][j], c);
    }
}

// Parallel bin scan: block per sample, 256 threads x 8 bins, descending order.
__global__ void scan_kernel(int pass) {
    const int b = blockIdx.x;
    const int t = threadIdx.x;
    const unsigned int* __restrict__ h = g_hist[pass][b];

    const int base = NB - 8 * (t + 1);         // thread t owns bins [base, base+8), t=0 = top
    unsigned int c[8], lsum = 0;
#pragma unroll
    for (int j = 0; j < 8; j++) { c[j] = h[base + j]; lsum += c[j]; }

    __shared__ unsigned int ssum[256];
    ssum[t] = lsum;
    __syncthreads();
    unsigned int v = lsum;
    for (int off = 1; off < 256; off <<= 1) {
        unsigned int u = (t >= off) ? ssum[t - off] : 0u;
        __syncthreads();
        v += u;
        ssum[t] = v;
        __syncthreads();
    }
    unsigned int ex = v - lsum;                // count in bins strictly above this segment

    const unsigned int k = (pass == 0) ? KSEL : g_krem[b];
    if (ex < k && ex + lsum >= k) {            // exactly one thread
        unsigned int cum = ex; int sel = 0; unsigned int kk = 0;
#pragma unroll
        for (int j = 7; j >= 0; j--) {
            cum += c[j];
            if (cum >= k) { sel = base + j; kk = k - (cum - c[j]); break; }
        }
        if (pass == 0) g_prefix[b] = ((unsigned int)sel) << 21;
        else           g_prefix[b] |= ((unsigned int)sel) << 10;
        g_krem[b] = kk;
    }
}

// Final scan over the 1024-bin low-digit histogram -> emits float threshold.
__global__ void final_scan_kernel() {
    const int b = blockIdx.x;
    const int t = threadIdx.x;
    const unsigned int* __restrict__ h = g_hist[2][b];

    const int base = 1024 - 4 * (t + 1);
    unsigned int c[4], lsum = 0;
#pragma unroll
    for (int j = 0; j < 4; j++) { c[j] = h[base + j]; lsum += c[j]; }

    __shared__ unsigned int ssum[256];
    ssum[t] = lsum;
    __syncthreads();
    unsigned int v = lsum;
    for (int off = 1; off < 256; off <<= 1) {
        unsigned int u = (t >= off) ? ssum[t - off] : 0u;
        __syncthreads();
        v += u;
        ssum[t] = v;
        __syncthreads();
    }
    unsigned int ex = v - lsum;

    const unsigned int k = g_krem[b];
    if (ex < k && ex + lsum >= k) {
        unsigned int cum = ex; int sel = 0;
#pragma unroll
        for (int j = 3; j >= 0; j--) {
            cum += c[j];
            if (cum >= k) { sel = base + j; break; }
        }
        unsigned int full = g_prefix[b] | (unsigned int)sel;
        unsigned int u = (full & 0x80000000u) ? (full ^ 0x80000000u) : ~full;
        g_thresh[b] = __uint_as_float(u);
    }
}

// Fused threshold + 3136x256 -> 256x3136 transpose, 32x32 shared tiles.
__global__ void mask_transpose_kernel(const float* __restrict__ x,
                                      float* __restrict__ out) {
    __shared__ float tile[32][33];
    const int b   = blockIdx.z;
    const float t = g_thresh[b];
    const int c0  = blockIdx.x * 32;
    const int hw0 = blockIdx.y * 32;
    const float* __restrict__ in = x + (size_t)b * DIM;
    float* __restrict__ o        = out + (size_t)b * DIM;

#pragma unroll
    for (int j = 0; j < 32; j += 8) {
        tile[threadIdx.y + j][threadIdx.x] =
            in[(size_t)(hw0 + threadIdx.y + j) * CH + c0 + threadIdx.x];
    }
    __syncthreads();
#pragma unroll
    for (int j = 0; j < 32; j += 8) {
        float v = tile[threadIdx.x][threadIdx.y + j];
        o[(size_t)(c0 + threadIdx.y + j) * HW + hw0 + threadIdx.x] =
            (v < t) ? 0.0f : v;
    }
}

extern "C" void kernel_launch(void* const* d_in, const int* in_sizes, int n_in,
                              void* d_out, int out_size) {
    const float* x = (const float*)d_in[0];
    float* out = (float*)d_out;

    zero_kernel<<<(3 * BATCH * NB + 255) / 256, 256>>>();

    hist0_kernel<<<dim3(32, BATCH), 256>>>(x);
    scan_kernel<<<BATCH, 256>>>(0);
    hist_kernel<1><<<dim3(32, BATCH), 256>>>(x);
    scan_kernel<<<BATCH, 256>>>(1);
    hist_kernel<2><<<dim3(32, BATCH), 256>>>(x);
    final_scan_kernel<<<BATCH, 256>>>();

    mask_transpose_kernel<<<dim3(CH / 32, HW / 32, BATCH), dim3(32, 8)>>>(x, out);
}